// round 2
// baseline (speedup 1.0000x reference)
#include <cuda_runtime.h>
#include <math.h>

#define BB 8
#define CC 256
#define HH 64
#define WWW 64
#define NHD 4
#define HD 64
#define NN (HH*WWW)        // 4096 queries
#define HP (HH/2)
#define WP (WWW/2)
#define MM (HP*WP)         // 1024 keys
#define CNT (CC*HH*WWW)    // 1048576 per-batch norm count
#define EPSV 1e-5f

// ---------------- scratch (device globals; no allocations allowed) ----------
__device__ float g_xn [BB*CC*NN];   // normalized input (B,C,H*W)
__device__ float g_xds[BB*CC*MM];   // pooled normalized input (B,C,M)
__device__ float g_q  [BB*CC*NN];   // Q (B, C=head*hd+d, N)
__device__ float g_k  [BB*HD*MM];   // K (B, d, M)
__device__ float g_v  [BB*HD*MM];   // V (B, d, M)
__device__ float g_ao [BB*CC*NN];   // attention output (B, C, N)
__device__ float g_part[BB*64*2];   // partial sums
__device__ float g_stats[BB*2];     // mean, rstd per batch

// ---------------- GroupNorm stage 1: partial sum / sumsq --------------------
__global__ void k_reduce1(const float* __restrict__ x){
    int b = blockIdx.x >> 6;
    int chunk = blockIdx.x & 63;
    const float* xb = x + (size_t)b*CNT + (size_t)chunk*(CNT/64);
    float s = 0.f, s2 = 0.f;
    for (int i = threadIdx.x; i < CNT/64; i += 256){
        float v = xb[i]; s += v; s2 += v*v;
    }
    __shared__ float sh0[256], sh1[256];
    sh0[threadIdx.x] = s; sh1[threadIdx.x] = s2; __syncthreads();
    for (int st = 128; st > 0; st >>= 1){
        if (threadIdx.x < st){
            sh0[threadIdx.x] += sh0[threadIdx.x+st];
            sh1[threadIdx.x] += sh1[threadIdx.x+st];
        }
        __syncthreads();
    }
    if (threadIdx.x == 0){
        g_part[blockIdx.x*2+0] = sh0[0];
        g_part[blockIdx.x*2+1] = sh1[0];
    }
}

// ---------------- GroupNorm stage 2: finalize mean / rstd -------------------
__global__ void k_reduce2(){
    int b = blockIdx.x;
    __shared__ float sh0[64], sh1[64];
    sh0[threadIdx.x] = g_part[(b*64+threadIdx.x)*2+0];
    sh1[threadIdx.x] = g_part[(b*64+threadIdx.x)*2+1];
    __syncthreads();
    if (threadIdx.x == 0){
        float a = 0.f, c = 0.f;
        for (int i = 0; i < 64; i++){ a += sh0[i]; c += sh1[i]; }
        float mean = a / (float)CNT;
        float var  = c / (float)CNT - mean*mean;
        g_stats[b*2+0] = mean;
        g_stats[b*2+1] = rsqrtf(var + EPSV);
    }
}

// ---------------- normalize + write xn + avgpool(2x2) -----------------------
__global__ void k_norm_pool(const float* __restrict__ x,
                            const float* __restrict__ gw,
                            const float* __restrict__ gb){
    int gid = blockIdx.x*256 + threadIdx.x;     // over B*C*HP*WP
    int pw = gid & (WP-1);
    int ph = (gid >> 5) & (HP-1);
    int c  = (gid >> 10) & (CC-1);
    int b  = gid >> 18;
    float mean = g_stats[b*2+0], rstd = g_stats[b*2+1];
    float w = gw[c]*rstd;
    float bias = gb[c] - mean*w;
    size_t base = ((size_t)(b*CC + c))*NN + (size_t)(2*ph)*WWW + 2*pw;
    float v00 = x[base]        * w + bias;
    float v01 = x[base+1]      * w + bias;
    float v10 = x[base+WWW]    * w + bias;
    float v11 = x[base+WWW+1]  * w + bias;
    g_xn[base]       = v00;
    g_xn[base+1]     = v01;
    g_xn[base+WWW]   = v10;
    g_xn[base+WWW+1] = v11;
    g_xds[((size_t)(b*CC+c))*MM + ph*WP + pw] = 0.25f*(v00+v01+v10+v11);
}

// ---------------- generic per-batch SGEMM: Out = W @ X (+resid+gamma) -------
// W: [OC][IC] row-major, X: [B][IC][NT], Out: [B][OC][NT]
// Tile 64x64, BK=16, 256 threads, 4x4 register blocking.
__global__ void k_gemm(const float* __restrict__ Wm, const float* __restrict__ X,
                       float* __restrict__ Out, int OC, int IC, int NT,
                       const float* __restrict__ resid, const float* __restrict__ gamma){
    __shared__ float Ws[16][64];
    __shared__ float Xs[16][64];
    int b  = blockIdx.z;
    const float* Xb = X + (size_t)b*IC*NT;
    int n0 = blockIdx.x*64, oc0 = blockIdx.y*64;
    int tid = threadIdx.x;
    int tx = tid & 15, ty = tid >> 4;
    int lw_oc = tid >> 2, lw_k = (tid & 3)*4;
    int lx_k = tid >> 4,  lx_n = (tid & 15)*4;
    float acc[4][4] = {};
    for (int k0 = 0; k0 < IC; k0 += 16){
        float4 wv = *(const float4*)&Wm[(size_t)(oc0+lw_oc)*IC + k0 + lw_k];
        Ws[lw_k+0][lw_oc] = wv.x;
        Ws[lw_k+1][lw_oc] = wv.y;
        Ws[lw_k+2][lw_oc] = wv.z;
        Ws[lw_k+3][lw_oc] = wv.w;
        *(float4*)&Xs[lx_k][lx_n] = *(const float4*)&Xb[(size_t)(k0+lx_k)*NT + n0 + lx_n];
        __syncthreads();
        #pragma unroll
        for (int kk = 0; kk < 16; kk++){
            float4 a  = *(const float4*)&Ws[kk][ty*4];
            float4 bb = *(const float4*)&Xs[kk][tx*4];
            float ar[4] = {a.x, a.y, a.z, a.w};
            float br[4] = {bb.x, bb.y, bb.z, bb.w};
            #pragma unroll
            for (int i = 0; i < 4; i++)
                #pragma unroll
                for (int j = 0; j < 4; j++)
                    acc[i][j] += ar[i]*br[j];
        }
        __syncthreads();
    }
    #pragma unroll
    for (int i = 0; i < 4; i++){
        int oc = oc0 + ty*4 + i;
        size_t row = ((size_t)b*OC + oc)*NT + n0 + tx*4;
        if (resid){
            float g = gamma[oc];
            float4 r = *(const float4*)&resid[row];
            float4 o = make_float4(r.x + g*acc[i][0], r.y + g*acc[i][1],
                                   r.z + g*acc[i][2], r.w + g*acc[i][3]);
            *(float4*)&Out[row] = o;
        } else {
            *(float4*)&Out[row] = make_float4(acc[i][0], acc[i][1], acc[i][2], acc[i][3]);
        }
    }
}

// ---------------- flash attention (fp32), BQ=64, key tiles of 64 ------------
// Q: g_q[b][head*64+d][n], K/V: g_k/g_v[b][d][m], out: g_ao[b][head*64+d][n]
#define ATT_F_QS  0                         // [64][64]  Qs[d][q]  (scaled)
#define ATT_F_KS  4096                      // [64][64]  Ks[d][k]
#define ATT_F_VS  8192                      // [64][68]  Vs[k][d]
#define ATT_F_SS  (8192 + 64*68)            // [64][65]  Ss[q][k]
#define ATT_F_PT  (ATT_F_SS + 64*65)        // [64][68]  Pt[k][q]
#define ATT_F_M   (ATT_F_PT + 64*68)        // [64]
#define ATT_F_L   (ATT_F_M + 64)            // [64]
#define ATT_F_A   (ATT_F_L + 64)            // [64]
#define ATT_F_RED (ATT_F_A + 64)            // [4][64]
#define ATT_FLOATS (ATT_F_RED + 256)
#define ATT_SMEM_BYTES (ATT_FLOATS*4)

__global__ void k_attn(){
    extern __shared__ float sm[];
    float* Qs  = sm + ATT_F_QS;
    float* Ks  = sm + ATT_F_KS;
    float* Vs  = sm + ATT_F_VS;
    float* Ss  = sm + ATT_F_SS;
    float* Pt  = sm + ATT_F_PT;
    float* mr  = sm + ATT_F_M;
    float* lr  = sm + ATT_F_L;
    float* ar  = sm + ATT_F_A;
    float* red = sm + ATT_F_RED;

    int b = blockIdx.z, head = blockIdx.y, qt = blockIdx.x;
    int tid = threadIdx.x, tx = tid & 15, ty = tid >> 4;
    const float scale = 0.125f;  // hd^-0.5, hd=64

    const float* qbase = g_q + ((size_t)b*CC + head*HD)*NN + (size_t)qt*64;
    const float* kbase = g_k + (size_t)b*HD*MM;
    const float* vbase = g_v + (size_t)b*HD*MM;

    {   // load Q tile (scaled), Qs[d][q]
        int q = tid & 63, dr = tid >> 6;
        #pragma unroll
        for (int r = 0; r < 16; r++){
            int d = dr + r*4;
            Qs[d*64 + q] = qbase[(size_t)d*NN + q] * scale;
        }
    }
    if (tid < 64){ mr[tid] = -1e30f; lr[tid] = 0.f; }
    float oacc[4][4] = {};
    __syncthreads();

    for (int m0 = 0; m0 < MM; m0 += 64){
        {   // load K tile Ks[d][k], V tile Vs[k][d]
            int k = tid & 63, dr = tid >> 6;
            #pragma unroll
            for (int r = 0; r < 16; r++){
                int d = dr + r*4;
                float kv = kbase[(size_t)d*MM + m0 + k];
                float vv = vbase[(size_t)d*MM + m0 + k];
                Ks[d*64 + k] = kv;
                Vs[k*68 + d] = vv;
            }
        }
        __syncthreads();

        // S = (scale*Q)^T K  -> Ss[q][k]
        float s[4][4] = {};
        #pragma unroll
        for (int kk = 0; kk < 64; kk++){
            float4 a  = *(const float4*)&Qs[kk*64 + ty*4];
            float4 bb = *(const float4*)&Ks[kk*64 + tx*4];
            float arx[4] = {a.x, a.y, a.z, a.w};
            float brx[4] = {bb.x, bb.y, bb.z, bb.w};
            #pragma unroll
            for (int i = 0; i < 4; i++)
                #pragma unroll
                for (int j = 0; j < 4; j++)
                    s[i][j] += arx[i]*brx[j];
        }
        #pragma unroll
        for (int i = 0; i < 4; i++)
            #pragma unroll
            for (int j = 0; j < 4; j++)
                Ss[(ty*4+i)*65 + tx*4+j] = s[i][j];
        __syncthreads();

        // online softmax
        int q = tid & 63, quarter = tid >> 6;
        float pm = -1e30f;
        #pragma unroll
        for (int r = 0; r < 16; r++)
            pm = fmaxf(pm, Ss[q*65 + quarter*16 + r]);
        red[quarter*64 + q] = pm;
        __syncthreads();
        if (tid < 64){
            float mt = fmaxf(fmaxf(red[tid], red[64+tid]), fmaxf(red[128+tid], red[192+tid]));
            float mo = mr[tid];
            float mn = fmaxf(mo, mt);
            mr[tid] = mn;
            ar[tid] = __expf(mo - mn);
        }
        __syncthreads();
        float mn = mr[q];
        float ps = 0.f;
        #pragma unroll
        for (int r = 0; r < 16; r++){
            int k = quarter*16 + r;
            float p = __expf(Ss[q*65 + k] - mn);
            Pt[k*68 + q] = p;
            ps += p;
        }
        red[quarter*64 + q] = ps;
        __syncthreads();
        if (tid < 64){
            float ls = red[tid] + red[64+tid] + red[128+tid] + red[192+tid];
            lr[tid] = lr[tid]*ar[tid] + ls;
        }
        float al[4];
        #pragma unroll
        for (int i = 0; i < 4; i++) al[i] = ar[ty*4+i];
        #pragma unroll
        for (int i = 0; i < 4; i++)
            #pragma unroll
            for (int j = 0; j < 4; j++)
                oacc[i][j] *= al[i];
        // O += P^T-staged V : both operands float4, conflict-free
        #pragma unroll
        for (int kk = 0; kk < 64; kk++){
            float4 a  = *(const float4*)&Pt[kk*68 + ty*4];
            float4 bb = *(const float4*)&Vs[kk*68 + tx*4];
            float arx[4] = {a.x, a.y, a.z, a.w};
            float brx[4] = {bb.x, bb.y, bb.z, bb.w};
            #pragma unroll
            for (int i = 0; i < 4; i++)
                #pragma unroll
                for (int j = 0; j < 4; j++)
                    oacc[i][j] += arx[i]*brx[j];
        }
        __syncthreads();
    }

    // finalize: divide by l, stage via smem, coalesced store
    float linv[4];
    #pragma unroll
    for (int i = 0; i < 4; i++) linv[i] = 1.f / lr[ty*4+i];
    #pragma unroll
    for (int i = 0; i < 4; i++)
        #pragma unroll
        for (int j = 0; j < 4; j++)
            Ss[(ty*4+i)*65 + tx*4+j] = oacc[i][j]*linv[i];
    __syncthreads();
    {
        int q = tid & 63, dr = tid >> 6;
        float* obase = g_ao + ((size_t)b*CC + head*HD)*NN + (size_t)qt*64;
        #pragma unroll
        for (int r = 0; r < 16; r++){
            int d = dr + r*4;
            obase[(size_t)d*NN + q] = Ss[q*65 + d];
        }
    }
}

// ---------------------------------------------------------------------------
extern "C" void kernel_launch(void* const* d_in, const int* in_sizes, int n_in,
                              void* d_out, int out_size){
    const float* x     = (const float*)d_in[0];
    const float* gn_w  = (const float*)d_in[1];
    const float* gn_b  = (const float*)d_in[2];
    const float* wq    = (const float*)d_in[3];
    const float* wk    = (const float*)d_in[4];
    const float* wv    = (const float*)d_in[5];
    const float* wo    = (const float*)d_in[6];
    const float* gamma = (const float*)d_in[7];
    float* out = (float*)d_out;

    void *p_xn, *p_xds, *p_q, *p_k, *p_v, *p_ao;
    cudaGetSymbolAddress(&p_xn,  g_xn);
    cudaGetSymbolAddress(&p_xds, g_xds);
    cudaGetSymbolAddress(&p_q,   g_q);
    cudaGetSymbolAddress(&p_k,   g_k);
    cudaGetSymbolAddress(&p_v,   g_v);
    cudaGetSymbolAddress(&p_ao,  g_ao);

    k_reduce1<<<BB*64, 256>>>(x);
    k_reduce2<<<BB, 64>>>();
    k_norm_pool<<<(BB*CC*MM)/256, 256>>>(x, gn_w, gn_b);

    k_gemm<<<dim3(NN/64, CC/64, BB), 256>>>(wq, (const float*)p_xn, (float*)p_q,
                                            CC, CC, NN, nullptr, nullptr);
    k_gemm<<<dim3(MM/64, 1, BB), 256>>>(wk, (const float*)p_xds, (float*)p_k,
                                        HD, CC, MM, nullptr, nullptr);
    k_gemm<<<dim3(MM/64, 1, BB), 256>>>(wv, (const float*)p_xds, (float*)p_v,
                                        HD, CC, MM, nullptr, nullptr);

    cudaFuncSetAttribute(k_attn, cudaFuncAttributeMaxDynamicSharedMemorySize, ATT_SMEM_BYTES);
    k_attn<<<dim3(NN/64, NHD, BB), 256, ATT_SMEM_BYTES>>>();

    k_gemm<<<dim3(NN/64, CC/64, BB), 256>>>(wo, (const float*)p_ao, out,
                                            CC, CC, NN, x, gamma);
}

// round 3
// speedup vs baseline: 2.4225x; 2.4225x over previous
#include <cuda_runtime.h>
#include <cuda_bf16.h>
#include <math.h>
#include <stdint.h>

#define BB 8
#define CC 256
#define HH 64
#define WWW 64
#define NHD 4
#define HD 64
#define NN (HH*WWW)        // 4096 queries
#define HP (HH/2)
#define WP (WWW/2)
#define MM (HP*WP)         // 1024 keys
#define CNT (CC*HH*WWW)    // 1048576 per-batch norm count
#define EPSV 1e-5f
#define QSCALE (0.125f * 1.44269504f)   // hd^-0.5 * log2(e), exp2-domain softmax

// ---------------- scratch (device globals; no allocations allowed) ----------
__device__ float g_xn [BB*CC*NN];   // normalized input (B,C,H*W)
__device__ float g_xds[BB*CC*MM];   // pooled normalized input (B,C,M)
__device__ float g_q  [BB*CC*NN];   // Q (B, C=head*hd+d, N) fp32
__device__ float g_k  [BB*HD*MM];   // K (B, d, M) fp32
__device__ float g_v  [BB*HD*MM];   // V (B, d, M) fp32
__device__ float g_ao [BB*CC*NN];   // attention output (B, C, N)
__device__ float g_part[BB*64*2];   // partial sums
__device__ float g_stats[BB*2];     // mean, rstd per batch
__device__ unsigned short g_kb[BB*MM*HD];  // K bf16 [b][m][d]
__device__ unsigned short g_vb[BB*HD*MM];  // V bf16 [b][d][m]

// ---------------- small helpers ---------------------------------------------
__device__ __forceinline__ float ex2(float x){
    float y; asm("ex2.approx.ftz.f32 %0, %1;" : "=f"(y) : "f"(x)); return y;
}
__device__ __forceinline__ uint32_t packbf(float lo, float hi){
    uint32_t r; asm("cvt.rn.bf16x2.f32 %0, %1, %2;" : "=r"(r) : "f"(hi), "f"(lo));
    return r;
}
__device__ __forceinline__ void mma16816(float* d, const uint32_t* a, uint32_t b0, uint32_t b1){
    asm volatile("mma.sync.aligned.m16n8k16.row.col.f32.bf16.bf16.f32 "
        "{%0,%1,%2,%3}, {%4,%5,%6,%7}, {%8,%9}, {%0,%1,%2,%3};\n"
        : "+f"(d[0]), "+f"(d[1]), "+f"(d[2]), "+f"(d[3])
        : "r"(a[0]), "r"(a[1]), "r"(a[2]), "r"(a[3]), "r"(b0), "r"(b1));
}

// ---------------- GroupNorm stage 1: partial sum / sumsq --------------------
__global__ void k_reduce1(const float* __restrict__ x){
    int b = blockIdx.x >> 6;
    int chunk = blockIdx.x & 63;
    const float* xb = x + (size_t)b*CNT + (size_t)chunk*(CNT/64);
    float s = 0.f, s2 = 0.f;
    for (int i = threadIdx.x; i < CNT/64; i += 256){
        float v = xb[i]; s += v; s2 += v*v;
    }
    __shared__ float sh0[256], sh1[256];
    sh0[threadIdx.x] = s; sh1[threadIdx.x] = s2; __syncthreads();
    for (int st = 128; st > 0; st >>= 1){
        if (threadIdx.x < st){
            sh0[threadIdx.x] += sh0[threadIdx.x+st];
            sh1[threadIdx.x] += sh1[threadIdx.x+st];
        }
        __syncthreads();
    }
    if (threadIdx.x == 0){
        g_part[blockIdx.x*2+0] = sh0[0];
        g_part[blockIdx.x*2+1] = sh1[0];
    }
}

// ---------------- GroupNorm stage 2: finalize mean / rstd -------------------
__global__ void k_reduce2(){
    int b = blockIdx.x;
    __shared__ float sh0[64], sh1[64];
    sh0[threadIdx.x] = g_part[(b*64+threadIdx.x)*2+0];
    sh1[threadIdx.x] = g_part[(b*64+threadIdx.x)*2+1];
    __syncthreads();
    if (threadIdx.x == 0){
        float a = 0.f, c = 0.f;
        for (int i = 0; i < 64; i++){ a += sh0[i]; c += sh1[i]; }
        float mean = a / (float)CNT;
        float var  = c / (float)CNT - mean*mean;
        g_stats[b*2+0] = mean;
        g_stats[b*2+1] = rsqrtf(var + EPSV);
    }
}

// ---------------- normalize + write xn + avgpool(2x2) -----------------------
__global__ void k_norm_pool(const float* __restrict__ x,
                            const float* __restrict__ gw,
                            const float* __restrict__ gb){
    int gid = blockIdx.x*256 + threadIdx.x;     // over B*C*HP*WP
    int pw = gid & (WP-1);
    int ph = (gid >> 5) & (HP-1);
    int c  = (gid >> 10) & (CC-1);
    int b  = gid >> 18;
    float mean = g_stats[b*2+0], rstd = g_stats[b*2+1];
    float w = gw[c]*rstd;
    float bias = gb[c] - mean*w;
    size_t base = ((size_t)(b*CC + c))*NN + (size_t)(2*ph)*WWW + 2*pw;
    float v00 = x[base]        * w + bias;
    float v01 = x[base+1]      * w + bias;
    float v10 = x[base+WWW]    * w + bias;
    float v11 = x[base+WWW+1]  * w + bias;
    g_xn[base]       = v00;
    g_xn[base+1]     = v01;
    g_xn[base+WWW]   = v10;
    g_xn[base+WWW+1] = v11;
    g_xds[((size_t)(b*CC+c))*MM + ph*WP + pw] = 0.25f*(v00+v01+v10+v11);
}

// ---------------- generic per-batch SGEMM: Out = W @ X (+resid+gamma) -------
__global__ void k_gemm(const float* __restrict__ Wm, const float* __restrict__ X,
                       float* __restrict__ Out, int OC, int IC, int NT,
                       const float* __restrict__ resid, const float* __restrict__ gamma){
    __shared__ float Ws[16][64];
    __shared__ float Xs[16][64];
    int b  = blockIdx.z;
    const float* Xb = X + (size_t)b*IC*NT;
    int n0 = blockIdx.x*64, oc0 = blockIdx.y*64;
    int tid = threadIdx.x;
    int tx = tid & 15, ty = tid >> 4;
    int lw_oc = tid >> 2, lw_k = (tid & 3)*4;
    int lx_k = tid >> 4,  lx_n = (tid & 15)*4;
    float acc[4][4] = {};
    for (int k0 = 0; k0 < IC; k0 += 16){
        float4 wv = *(const float4*)&Wm[(size_t)(oc0+lw_oc)*IC + k0 + lw_k];
        Ws[lw_k+0][lw_oc] = wv.x;
        Ws[lw_k+1][lw_oc] = wv.y;
        Ws[lw_k+2][lw_oc] = wv.z;
        Ws[lw_k+3][lw_oc] = wv.w;
        *(float4*)&Xs[lx_k][lx_n] = *(const float4*)&Xb[(size_t)(k0+lx_k)*NT + n0 + lx_n];
        __syncthreads();
        #pragma unroll
        for (int kk = 0; kk < 16; kk++){
            float4 a  = *(const float4*)&Ws[kk][ty*4];
            float4 bb = *(const float4*)&Xs[kk][tx*4];
            float ar[4] = {a.x, a.y, a.z, a.w};
            float br[4] = {bb.x, bb.y, bb.z, bb.w};
            #pragma unroll
            for (int i = 0; i < 4; i++)
                #pragma unroll
                for (int j = 0; j < 4; j++)
                    acc[i][j] += ar[i]*br[j];
        }
        __syncthreads();
    }
    #pragma unroll
    for (int i = 0; i < 4; i++){
        int oc = oc0 + ty*4 + i;
        size_t row = ((size_t)b*OC + oc)*NT + n0 + tx*4;
        if (resid){
            float g = gamma[oc];
            float4 r = *(const float4*)&resid[row];
            float4 o = make_float4(r.x + g*acc[i][0], r.y + g*acc[i][1],
                                   r.z + g*acc[i][2], r.w + g*acc[i][3]);
            *(float4*)&Out[row] = o;
        } else {
            *(float4*)&Out[row] = make_float4(acc[i][0], acc[i][1], acc[i][2], acc[i][3]);
        }
    }
}

// ---------------- convert K: fp32 [b][d][m] -> bf16 [b][m][d] ----------------
__global__ void k_convK(){
    __shared__ float T[64*65];
    int tid = threadIdx.x;
    int b = blockIdx.y, m0 = blockIdx.x*64;
    for (int i = tid; i < 4096; i += 256){
        int m = i & 63, d = i >> 6;
        T[m*65 + d] = g_k[((size_t)b*HD + d)*MM + m0 + m];
    }
    __syncthreads();
    uint32_t* dst = (uint32_t*)g_kb;
    for (int i = tid; i < 2048; i += 256){
        int m = i >> 5, dp = i & 31;
        dst[((size_t)b*MM + m0 + m)*32 + dp] = packbf(T[m*65 + 2*dp], T[m*65 + 2*dp + 1]);
    }
}

// ---------------- convert V: fp32 [b][d][m] -> bf16 same layout --------------
__global__ void k_convV(){
    int i = blockIdx.x*256 + threadIdx.x;   // over BB*HD*MM/4
    float4 v = ((const float4*)g_v)[i];
    uint2 o; o.x = packbf(v.x, v.y); o.y = packbf(v.z, v.w);
    ((uint2*)g_vb)[i] = o;
}

// ---------------- flash attention, bf16 mma.sync ----------------------------
// Block: 4 warps x 16 q rows = 64 q. 16 key tiles of 64.
__global__ void __launch_bounds__(128) k_attn_mma(){
    __shared__ __align__(16) unsigned short Qs[64*72];
    __shared__ __align__(16) unsigned char Ubuf[2*64*72*2];  // 18432B union
    unsigned short* Ks = (unsigned short*)Ubuf;
    unsigned short* Vs = Ks + 64*72;
    float* Os = (float*)Ubuf;                                // epilogue reuse

    int tid = threadIdx.x;
    int warp = tid >> 5, lane = tid & 31;
    int g = lane >> 2, tig = lane & 3;
    int b = blockIdx.z, h = blockIdx.y, qt = blockIdx.x;
    int q0 = warp*16;

    // ---- load Q tile: transpose + scale + cvt  (g_q[b][h*64+d][n] -> Qs[n][d])
    const float* qsrc = g_q + ((size_t)(b*CC + h*HD))*NN + (size_t)qt*64;
    for (int i = tid; i < 4096; i += 128){
        int n = i & 63, d = i >> 6;
        Qs[n*72 + d] = __bfloat16_as_ushort(__float2bfloat16(qsrc[(size_t)d*NN + n] * QSCALE));
    }
    __syncthreads();

    // preload Q fragments (16 regs), Qs not needed afterwards
    uint32_t aq[4][4];
    {
        const unsigned short* r0 = Qs + (q0+g)*72;
        const unsigned short* r8 = Qs + (q0+g+8)*72;
        #pragma unroll
        for (int kk = 0; kk < 4; kk++){
            aq[kk][0] = *(const uint32_t*)&r0[kk*16 + tig*2];
            aq[kk][1] = *(const uint32_t*)&r8[kk*16 + tig*2];
            aq[kk][2] = *(const uint32_t*)&r0[kk*16 + tig*2 + 8];
            aq[kk][3] = *(const uint32_t*)&r8[kk*16 + tig*2 + 8];
        }
    }

    float m0 = -1e30f, m1 = -1e30f, l0 = 0.f, l1 = 0.f;
    float o[8][4];
    #pragma unroll
    for (int j = 0; j < 8; j++){ o[j][0]=0.f; o[j][1]=0.f; o[j][2]=0.f; o[j][3]=0.f; }

    const int4* kall = (const int4*)(g_kb + (size_t)b*MM*HD);
    const unsigned short* vall = g_vb + (size_t)b*HD*MM;

    for (int mt = 0; mt < MM/64; mt++){
        int base = mt*64;
        __syncthreads();
        // K tile: Kb rows (base+r), 64 bf16 each = 8 int4
        for (int i = tid; i < 512; i += 128){
            int r = i >> 3, c = i & 7;
            *(int4*)&Ks[r*72 + c*8] = kall[(size_t)(base + r)*8 + c];
        }
        // V tile: Vb rows d=r, cols base..base+63
        for (int i = tid; i < 512; i += 128){
            int r = i >> 3, c = i & 7;
            *(int4*)&Vs[r*72 + c*8] = *(const int4*)&vall[(size_t)r*MM + base + c*8];
        }
        __syncthreads();

        // ---- S = Q K^T (exp2 domain, scale pre-folded)
        float s[8][4];
        #pragma unroll
        for (int j = 0; j < 8; j++){ s[j][0]=0.f; s[j][1]=0.f; s[j][2]=0.f; s[j][3]=0.f; }
        #pragma unroll
        for (int kk = 0; kk < 4; kk++){
            #pragma unroll
            for (int j = 0; j < 8; j++){
                const unsigned short* kr = Ks + (8*j + g)*72 + kk*16 + tig*2;
                uint32_t b0 = *(const uint32_t*)kr;
                uint32_t b1 = *(const uint32_t*)(kr + 8);
                mma16816(s[j], aq[kk], b0, b1);
            }
        }

        // ---- online softmax (rows g and g+8 of this warp's 16-row band)
        float mx0 = -1e30f, mx1 = -1e30f;
        #pragma unroll
        for (int j = 0; j < 8; j++){
            mx0 = fmaxf(mx0, fmaxf(s[j][0], s[j][1]));
            mx1 = fmaxf(mx1, fmaxf(s[j][2], s[j][3]));
        }
        mx0 = fmaxf(mx0, __shfl_xor_sync(0xffffffffu, mx0, 1));
        mx0 = fmaxf(mx0, __shfl_xor_sync(0xffffffffu, mx0, 2));
        mx1 = fmaxf(mx1, __shfl_xor_sync(0xffffffffu, mx1, 1));
        mx1 = fmaxf(mx1, __shfl_xor_sync(0xffffffffu, mx1, 2));
        float mn0 = fmaxf(m0, mx0), mn1 = fmaxf(m1, mx1);
        float al0 = ex2(m0 - mn0), al1 = ex2(m1 - mn1);
        m0 = mn0; m1 = mn1;

        uint32_t plo[8], phi[8];
        float sum0 = 0.f, sum1 = 0.f;
        #pragma unroll
        for (int j = 0; j < 8; j++){
            float p0 = ex2(s[j][0] - mn0), p1 = ex2(s[j][1] - mn0);
            float p2 = ex2(s[j][2] - mn1), p3 = ex2(s[j][3] - mn1);
            sum0 += p0 + p1; sum1 += p2 + p3;
            plo[j] = packbf(p0, p1);
            phi[j] = packbf(p2, p3);
        }
        sum0 += __shfl_xor_sync(0xffffffffu, sum0, 1);
        sum0 += __shfl_xor_sync(0xffffffffu, sum0, 2);
        sum1 += __shfl_xor_sync(0xffffffffu, sum1, 1);
        sum1 += __shfl_xor_sync(0xffffffffu, sum1, 2);
        l0 = l0*al0 + sum0;
        l1 = l1*al1 + sum1;
        #pragma unroll
        for (int j = 0; j < 8; j++){
            o[j][0] *= al0; o[j][1] *= al0; o[j][2] *= al1; o[j][3] *= al1;
        }

        // ---- O += P V  (P a-fragments come straight from S accum layout)
        #pragma unroll
        for (int kk = 0; kk < 4; kk++){
            uint32_t af[4] = { plo[2*kk], phi[2*kk], plo[2*kk+1], phi[2*kk+1] };
            #pragma unroll
            for (int j = 0; j < 8; j++){
                const unsigned short* vr = Vs + (8*j + g)*72 + kk*16 + tig*2;
                uint32_t b0 = *(const uint32_t*)vr;
                uint32_t b1 = *(const uint32_t*)(vr + 8);
                mma16816(o[j], af, b0, b1);
            }
        }
    }

    // ---- finalize: /l, stage via smem, coalesced transposed store to g_ao
    float il0 = 1.f / l0, il1 = 1.f / l1;
    __syncthreads();   // done reading Ks/Vs; safe to overwrite as Os
    #pragma unroll
    for (int j = 0; j < 8; j++){
        Os[(q0+g  )*65 + 8*j + 2*tig    ] = o[j][0]*il0;
        Os[(q0+g  )*65 + 8*j + 2*tig + 1] = o[j][1]*il0;
        Os[(q0+g+8)*65 + 8*j + 2*tig    ] = o[j][2]*il1;
        Os[(q0+g+8)*65 + 8*j + 2*tig + 1] = o[j][3]*il1;
    }
    __syncthreads();
    float* aodst = g_ao + ((size_t)(b*CC + h*HD))*NN + (size_t)qt*64;
    for (int i = tid; i < 4096; i += 128){
        int n = i & 63, d = i >> 6;
        aodst[(size_t)d*NN + n] = Os[n*65 + d];
    }
}

// ---------------------------------------------------------------------------
extern "C" void kernel_launch(void* const* d_in, const int* in_sizes, int n_in,
                              void* d_out, int out_size){
    const float* x     = (const float*)d_in[0];
    const float* gn_w  = (const float*)d_in[1];
    const float* gn_b  = (const float*)d_in[2];
    const float* wq    = (const float*)d_in[3];
    const float* wk    = (const float*)d_in[4];
    const float* wv    = (const float*)d_in[5];
    const float* wo    = (const float*)d_in[6];
    const float* gamma = (const float*)d_in[7];
    float* out = (float*)d_out;

    void *p_xn, *p_xds, *p_q, *p_k, *p_v, *p_ao;
    cudaGetSymbolAddress(&p_xn,  g_xn);
    cudaGetSymbolAddress(&p_xds, g_xds);
    cudaGetSymbolAddress(&p_q,   g_q);
    cudaGetSymbolAddress(&p_k,   g_k);
    cudaGetSymbolAddress(&p_v,   g_v);
    cudaGetSymbolAddress(&p_ao,  g_ao);

    k_reduce1<<<BB*64, 256>>>(x);
    k_reduce2<<<BB, 64>>>();
    k_norm_pool<<<(BB*CC*MM)/256, 256>>>(x, gn_w, gn_b);

    k_gemm<<<dim3(NN/64, CC/64, BB), 256>>>(wq, (const float*)p_xn, (float*)p_q,
                                            CC, CC, NN, nullptr, nullptr);
    k_gemm<<<dim3(MM/64, 1, BB), 256>>>(wk, (const float*)p_xds, (float*)p_k,
                                        HD, CC, MM, nullptr, nullptr);
    k_gemm<<<dim3(MM/64, 1, BB), 256>>>(wv, (const float*)p_xds, (float*)p_v,
                                        HD, CC, MM, nullptr, nullptr);

    k_convK<<<dim3(MM/64, BB), 256>>>();
    k_convV<<<(BB*HD*MM)/(256*4), 256>>>();

    k_attn_mma<<<dim3(NN/64, NHD, BB), 128>>>();

    k_gemm<<<dim3(NN/64, CC/64, BB), 256>>>(wo, (const float*)p_ao, out,
                                            CC, CC, NN, x, gamma);
}

// round 8
// speedup vs baseline: 4.2367x; 1.7489x over previous
#include <cuda_runtime.h>
#include <cuda_bf16.h>
#include <math.h>
#include <stdint.h>

#define BB 8
#define CC 256
#define HH 64
#define WWW 64
#define NHD 4
#define HD 64
#define NN (HH*WWW)        // 4096 queries
#define HP (HH/2)
#define WP (WWW/2)
#define MM (HP*WP)         // 1024 keys
#define CNT (CC*HH*WWW)
#define EPSV 1e-5f
#define QSCALE (0.125f * 1.44269504f)   // hd^-0.5 * log2(e); folded into wq

typedef unsigned short ushort_t;

// ---------------- scratch (device globals) ----------------------------------
__device__ ushort_t g_xnb [BB*NN*CC];   // xn bf16 [b][n][c]
__device__ ushort_t g_xdsb[BB*MM*CC];   // pooled bf16 [b][m][c]
__device__ ushort_t g_qb  [BB*NN*CC];   // Q bf16 [b][n][c]  (scale folded)
__device__ ushort_t g_kb  [BB*MM*HD];   // K bf16 [b][m][d]
__device__ ushort_t g_vb  [BB*HD*MM];   // V bf16 [b][d][m]
__device__ ushort_t g_aob [BB*NN*CC];   // attn out bf16 [b][n][c]
__device__ ushort_t g_wqb[CC*CC], g_wkb[HD*CC], g_wvb[HD*CC], g_wob[CC*CC];
__device__ float g_part[BB*64*2];
__device__ float g_stats[BB*2];

// ---------------- helpers ----------------------------------------------------
__device__ __forceinline__ float ex2(float x){
    float y; asm("ex2.approx.ftz.f32 %0, %1;" : "=f"(y) : "f"(x)); return y;
}
__device__ __forceinline__ uint32_t packbf(float lo, float hi){
    uint32_t r; asm("cvt.rn.bf16x2.f32 %0, %1, %2;" : "=r"(r) : "f"(hi), "f"(lo));
    return r;
}
__device__ __forceinline__ void mma16816(float* d, const uint32_t* a, uint32_t b0, uint32_t b1){
    asm volatile("mma.sync.aligned.m16n8k16.row.col.f32.bf16.bf16.f32 "
        "{%0,%1,%2,%3}, {%4,%5,%6,%7}, {%8,%9}, {%0,%1,%2,%3};\n"
        : "+f"(d[0]), "+f"(d[1]), "+f"(d[2]), "+f"(d[3])
        : "r"(a[0]), "r"(a[1]), "r"(a[2]), "r"(a[3]), "r"(b0), "r"(b1));
}

// ---------------- GroupNorm reductions ---------------------------------------
__global__ void k_reduce1(const float* __restrict__ x){
    int b = blockIdx.x >> 6;
    int chunk = blockIdx.x & 63;
    const float* xb = x + (size_t)b*CNT + (size_t)chunk*(CNT/64);
    float s = 0.f, s2 = 0.f;
    for (int i = threadIdx.x; i < CNT/64; i += 256){
        float v = xb[i]; s += v; s2 += v*v;
    }
    __shared__ float sh0[256], sh1[256];
    sh0[threadIdx.x] = s; sh1[threadIdx.x] = s2; __syncthreads();
    for (int st = 128; st > 0; st >>= 1){
        if (threadIdx.x < st){
            sh0[threadIdx.x] += sh0[threadIdx.x+st];
            sh1[threadIdx.x] += sh1[threadIdx.x+st];
        }
        __syncthreads();
    }
    if (threadIdx.x == 0){
        g_part[blockIdx.x*2+0] = sh0[0];
        g_part[blockIdx.x*2+1] = sh1[0];
    }
}

__global__ void k_reduce2(){
    int b = blockIdx.x;
    __shared__ float sh0[64], sh1[64];
    sh0[threadIdx.x] = g_part[(b*64+threadIdx.x)*2+0];
    sh1[threadIdx.x] = g_part[(b*64+threadIdx.x)*2+1];
    __syncthreads();
    if (threadIdx.x == 0){
        float a = 0.f, c = 0.f;
        for (int i = 0; i < 64; i++){ a += sh0[i]; c += sh1[i]; }
        float mean = a / (float)CNT;
        float var  = c / (float)CNT - mean*mean;
        g_stats[b*2+0] = mean;
        g_stats[b*2+1] = rsqrtf(var + EPSV);
    }
}

// ---------------- weight convert (optional scale fold) -----------------------
__global__ void k_cvtw(const float4* __restrict__ s, uint2* __restrict__ d, int n4, float sc){
    int i = blockIdx.x*256 + threadIdx.x;
    if (i >= n4) return;
    float4 v = s[i];
    uint2 o; o.x = packbf(v.x*sc, v.y*sc); o.y = packbf(v.z*sc, v.w*sc);
    d[i] = o;
}

// ---------------- fused normalize + transpose-to-bf16 + 2x2 pool -------------
// grid (HH/2, CC/64, BB), 256 threads.
__global__ void __launch_bounds__(256) k_normt(const float* __restrict__ x,
        const float* __restrict__ gw, const float* __restrict__ gb){
    __shared__ float T[64*65];
    int tid = threadIdx.x;
    int pw = tid & 31, cl = tid >> 5;          // pw: 0..31, cl: 0..7
    int b = blockIdx.z, ct = blockIdx.y, hp = blockIdx.x;
    float mean = g_stats[b*2], rstd = g_stats[b*2+1];
    float wv[8], bv[8], pacc[8];
    #pragma unroll
    for (int i = 0; i < 8; i++){
        int c = ct*64 + cl*8 + i;
        float w = gw[c]*rstd;
        wv[i] = w; bv[i] = gb[c] - mean*w;
        pacc[i] = 0.f;
    }
    uint32_t* xnb32 = (uint32_t*)g_xnb;
    for (int hh = 0; hh < 2; hh++){
        int h = hp*2 + hh;
        #pragma unroll
        for (int i = 0; i < 8; i++){
            int c = ct*64 + cl*8 + i;
            float2 xv = *(const float2*)&x[((size_t)(b*CC + c))*NN + h*64 + 2*pw];
            float v0 = xv.x*wv[i] + bv[i];
            float v1 = xv.y*wv[i] + bv[i];
            pacc[i] += v0 + v1;
            T[(2*pw)*65   + cl*8 + i] = v0;
            T[(2*pw+1)*65 + cl*8 + i] = v1;
        }
        __syncthreads();
        for (int j = tid; j < 2048; j += 256){
            int w = j >> 5, cp = j & 31;
            xnb32[((size_t)(b*NN) + h*64 + w)*128 + ct*32 + cp]
                = packbf(T[w*65 + 2*cp], T[w*65 + 2*cp + 1]);
        }
        __syncthreads();
    }
    int m = hp*32 + pw;
    uint32_t* dst = (uint32_t*)g_xdsb + ((size_t)(b*MM) + m)*128 + ct*32 + cl*4;
    #pragma unroll
    for (int p = 0; p < 4; p++)
        dst[p] = packbf(pacc[2*p]*0.25f, pacc[2*p+1]*0.25f);
}

// ---------------- bf16 MMA GEMM: D[M][N] = A[M][256] . B[N][256]^T -----------
// MODE 0: D bf16 [M][N].  MODE 1: D fp32, D = resid + gamma[row]*acc.
template<int BM, int BN, int MODE>
__global__ void __launch_bounds__((BM/64)*(BN/32)*32) k_mma(
        const ushort_t* __restrict__ A, const ushort_t* __restrict__ B,
        void* __restrict__ D, size_t sA, size_t sB, size_t sD, int Ndim,
        const float* __restrict__ resid, const float* __restrict__ gamma){
    const int T = (BM/64)*(BN/32)*32;
    const int nWN = BN/32;
    __shared__ ushort_t As[BM*40];
    __shared__ ushort_t Bs[BN*40];
    int tid = threadIdx.x, warp = tid >> 5, lane = tid & 31;
    int g = lane >> 2, tig = lane & 3;
    int wm = warp / nWN, wn = warp % nWN;
    int m0 = blockIdx.y*BM, n0 = blockIdx.x*BN;
    const ushort_t* Ab = A + (size_t)blockIdx.z*sA;
    const ushort_t* Bb = B + (size_t)blockIdx.z*sB;

    float acc[4][4][4];
    #pragma unroll
    for (int mt = 0; mt < 4; mt++)
        #pragma unroll
        for (int nt = 0; nt < 4; nt++){
            acc[mt][nt][0]=0.f; acc[mt][nt][1]=0.f; acc[mt][nt][2]=0.f; acc[mt][nt][3]=0.f;
        }

    for (int k0 = 0; k0 < 256; k0 += 32){
        for (int i = tid; i < BM*4; i += T){
            int r = i >> 2, c = i & 3;
            *(int4*)&As[r*40 + c*8] = *(const int4*)&Ab[(size_t)(m0 + r)*256 + k0 + c*8];
        }
        for (int i = tid; i < BN*4; i += T){
            int r = i >> 2, c = i & 3;
            *(int4*)&Bs[r*40 + c*8] = *(const int4*)&Bb[(size_t)(n0 + r)*256 + k0 + c*8];
        }
        __syncthreads();
        #pragma unroll
        for (int kk = 0; kk < 32; kk += 16){
            uint32_t af[4][4], bf[4][2];
            #pragma unroll
            for (int mt = 0; mt < 4; mt++){
                const ushort_t* p = &As[(wm*64 + mt*16 + g)*40 + kk + tig*2];
                af[mt][0] = *(const uint32_t*)p;
                af[mt][1] = *(const uint32_t*)(p + 8*40);
                af[mt][2] = *(const uint32_t*)(p + 8);
                af[mt][3] = *(const uint32_t*)(p + 8*40 + 8);
            }
            #pragma unroll
            for (int nt = 0; nt < 4; nt++){
                const ushort_t* p = &Bs[(wn*32 + nt*8 + g)*40 + kk + tig*2];
                bf[nt][0] = *(const uint32_t*)p;
                bf[nt][1] = *(const uint32_t*)(p + 8);
            }
            #pragma unroll
            for (int mt = 0; mt < 4; mt++)
                #pragma unroll
                for (int nt = 0; nt < 4; nt++)
                    mma16816(acc[mt][nt], af[mt], bf[nt][0], bf[nt][1]);
        }
        __syncthreads();
    }

    if (MODE == 0){
        uint32_t* Db = (uint32_t*)D + (size_t)blockIdx.z*(sD >> 1);
        int ldd = Ndim >> 1;
        #pragma unroll
        for (int mt = 0; mt < 4; mt++){
            int row = m0 + wm*64 + mt*16 + g;
            #pragma unroll
            for (int nt = 0; nt < 4; nt++){
                int col = (n0 + wn*32 + nt*8 + tig*2) >> 1;
                Db[(size_t)row*ldd + col]     = packbf(acc[mt][nt][0], acc[mt][nt][1]);
                Db[(size_t)(row+8)*ldd + col] = packbf(acc[mt][nt][2], acc[mt][nt][3]);
            }
        }
    } else {
        float* Df = (float*)D + (size_t)blockIdx.z*sD;
        const float* Rf = resid + (size_t)blockIdx.z*sD;
        #pragma unroll
        for (int mt = 0; mt < 4; mt++){
            int row = m0 + wm*64 + mt*16 + g;
            float g0 = gamma[row], g1 = gamma[row+8];
            #pragma unroll
            for (int nt = 0; nt < 4; nt++){
                int col = n0 + wn*32 + nt*8 + tig*2;
                float2 r0 = *(const float2*)&Rf[(size_t)row*Ndim + col];
                float2 r1 = *(const float2*)&Rf[(size_t)(row+8)*Ndim + col];
                float2 o0 = make_float2(r0.x + g0*acc[mt][nt][0], r0.y + g0*acc[mt][nt][1]);
                float2 o1 = make_float2(r1.x + g1*acc[mt][nt][2], r1.y + g1*acc[mt][nt][3]);
                *(float2*)&Df[(size_t)row*Ndim + col]     = o0;
                *(float2*)&Df[(size_t)(row+8)*Ndim + col] = o1;
            }
        }
    }
}

// ---------------- flash attention, bf16 mma, 128 q per block -----------------
__global__ void __launch_bounds__(256) k_attn_mma(){
    __shared__ __align__(16) ushort_t Qs[128*72];
    __shared__ __align__(16) ushort_t Ks[64*72];
    __shared__ __align__(16) ushort_t Vs[64*72];

    int tid = threadIdx.x;
    int warp = tid >> 5, lane = tid & 31;
    int g = lane >> 2, tig = lane & 3;
    int b = blockIdx.z, h = blockIdx.y, n0 = blockIdx.x*128;
    int q0 = warp*16;

    // Q tile: direct bf16 rows from g_qb[b][n][c], head slice
    const ushort_t* qsrc = g_qb + ((size_t)(b*NN) + n0)*CC + h*HD;
    for (int i = tid; i < 128*8; i += 256){
        int r = i >> 3, c = i & 7;
        *(int4*)&Qs[r*72 + c*8] = *(const int4*)&qsrc[(size_t)r*CC + c*8];
    }
    __syncthreads();

    uint32_t aq[4][4];
    {
        const ushort_t* r0 = Qs + (q0+g)*72;
        const ushort_t* r8 = r0 + 8*72;
        #pragma unroll
        for (int kk = 0; kk < 4; kk++){
            aq[kk][0] = *(const uint32_t*)&r0[kk*16 + tig*2];
            aq[kk][1] = *(const uint32_t*)&r8[kk*16 + tig*2];
            aq[kk][2] = *(const uint32_t*)&r0[kk*16 + tig*2 + 8];
            aq[kk][3] = *(const uint32_t*)&r8[kk*16 + tig*2 + 8];
        }
    }

    float m0 = -1e30f, m1 = -1e30f, l0 = 0.f, l1 = 0.f;
    float o[8][4];
    #pragma unroll
    for (int j = 0; j < 8; j++){ o[j][0]=0.f; o[j][1]=0.f; o[j][2]=0.f; o[j][3]=0.f; }

    const int4* kall = (const int4*)(g_kb + (size_t)b*MM*HD);
    const ushort_t* vall = g_vb + (size_t)b*HD*MM;

    for (int mt = 0; mt < MM/64; mt++){
        int base = mt*64;
        __syncthreads();
        for (int i = tid; i < 512; i += 256){
            int r = i >> 3, c = i & 7;
            *(int4*)&Ks[r*72 + c*8] = kall[(size_t)(base + r)*8 + c];
        }
        for (int i = tid; i < 512; i += 256){
            int r = i >> 3, c = i & 7;
            *(int4*)&Vs[r*72 + c*8] = *(const int4*)&vall[(size_t)r*MM + base + c*8];
        }
        __syncthreads();

        float s[8][4];
        #pragma unroll
        for (int j = 0; j < 8; j++){ s[j][0]=0.f; s[j][1]=0.f; s[j][2]=0.f; s[j][3]=0.f; }
        #pragma unroll
        for (int kk = 0; kk < 4; kk++){
            #pragma unroll
            for (int j = 0; j < 8; j++){
                const ushort_t* kr = Ks + (8*j + g)*72 + kk*16 + tig*2;
                uint32_t b0 = *(const uint32_t*)kr;
                uint32_t b1 = *(const uint32_t*)(kr + 8);
                mma16816(s[j], aq[kk], b0, b1);
            }
        }

        float mx0 = -1e30f, mx1 = -1e30f;
        #pragma unroll
        for (int j = 0; j < 8; j++){
            mx0 = fmaxf(mx0, fmaxf(s[j][0], s[j][1]));
            mx1 = fmaxf(mx1, fmaxf(s[j][2], s[j][3]));
        }
        mx0 = fmaxf(mx0, __shfl_xor_sync(0xffffffffu, mx0, 1));
        mx0 = fmaxf(mx0, __shfl_xor_sync(0xffffffffu, mx0, 2));
        mx1 = fmaxf(mx1, __shfl_xor_sync(0xffffffffu, mx1, 1));
        mx1 = fmaxf(mx1, __shfl_xor_sync(0xffffffffu, mx1, 2));
        float mn0 = fmaxf(m0, mx0), mn1 = fmaxf(m1, mx1);
        float al0 = ex2(m0 - mn0), al1 = ex2(m1 - mn1);
        m0 = mn0; m1 = mn1;

        uint32_t plo[8], phi[8];
        float sum0 = 0.f, sum1 = 0.f;
        #pragma unroll
        for (int j = 0; j < 8; j++){
            float p0 = ex2(s[j][0] - mn0), p1 = ex2(s[j][1] - mn0);
            float p2 = ex2(s[j][2] - mn1), p3 = ex2(s[j][3] - mn1);
            sum0 += p0 + p1; sum1 += p2 + p3;
            plo[j] = packbf(p0, p1);
            phi[j] = packbf(p2, p3);
        }
        sum0 += __shfl_xor_sync(0xffffffffu, sum0, 1);
        sum0 += __shfl_xor_sync(0xffffffffu, sum0, 2);
        sum1 += __shfl_xor_sync(0xffffffffu, sum1, 1);
        sum1 += __shfl_xor_sync(0xffffffffu, sum1, 2);
        l0 = l0*al0 + sum0;
        l1 = l1*al1 + sum1;
        #pragma unroll
        for (int j = 0; j < 8; j++){
            o[j][0] *= al0; o[j][1] *= al0; o[j][2] *= al1; o[j][3] *= al1;
        }

        #pragma unroll
        for (int kk = 0; kk < 4; kk++){
            uint32_t af[4] = { plo[2*kk], phi[2*kk], plo[2*kk+1], phi[2*kk+1] };
            #pragma unroll
            for (int j = 0; j < 8; j++){
                const ushort_t* vr = Vs + (8*j + g)*72 + kk*16 + tig*2;
                uint32_t b0 = *(const uint32_t*)vr;
                uint32_t b1 = *(const uint32_t*)(vr + 8);
                mma16816(o[j], af, b0, b1);
            }
        }
    }

    // epilogue: /l, pack, direct bf16 store to g_aob[b][n][c]
    float il0 = 1.f / l0, il1 = 1.f / l1;
    uint32_t* dst = (uint32_t*)g_aob + ((size_t)(b*NN) + n0)*128 + h*32;
    #pragma unroll
    for (int j = 0; j < 8; j++){
        dst[(size_t)(q0+g)*128   + 4*j + tig] = packbf(o[j][0]*il0, o[j][1]*il0);
        dst[(size_t)(q0+g+8)*128 + 4*j + tig] = packbf(o[j][2]*il1, o[j][3]*il1);
    }
}

// ---------------------------------------------------------------------------
extern "C" void kernel_launch(void* const* d_in, const int* in_sizes, int n_in,
                              void* d_out, int out_size){
    const float* x     = (const float*)d_in[0];
    const float* gn_w  = (const float*)d_in[1];
    const float* gn_b  = (const float*)d_in[2];
    const float* wq    = (const float*)d_in[3];
    const float* wk    = (const float*)d_in[4];
    const float* wv    = (const float*)d_in[5];
    const float* wo    = (const float*)d_in[6];
    const float* gamma = (const float*)d_in[7];
    float* out = (float*)d_out;

    void *p_xnb, *p_xdsb, *p_qb, *p_kb, *p_vb, *p_aob;
    void *p_wqb, *p_wkb, *p_wvb, *p_wob;
    cudaGetSymbolAddress(&p_xnb,  g_xnb);
    cudaGetSymbolAddress(&p_xdsb, g_xdsb);
    cudaGetSymbolAddress(&p_qb,   g_qb);
    cudaGetSymbolAddress(&p_kb,   g_kb);
    cudaGetSymbolAddress(&p_vb,   g_vb);
    cudaGetSymbolAddress(&p_aob,  g_aob);
    cudaGetSymbolAddress(&p_wqb,  g_wqb);
    cudaGetSymbolAddress(&p_wkb,  g_wkb);
    cudaGetSymbolAddress(&p_wvb,  g_wvb);
    cudaGetSymbolAddress(&p_wob,  g_wob);

    k_reduce1<<<BB*64, 256>>>(x);
    k_reduce2<<<BB, 64>>>();

    k_cvtw<<<(CC*CC/4+255)/256, 256>>>((const float4*)wq, (uint2*)p_wqb, CC*CC/4, QSCALE);
    k_cvtw<<<(HD*CC/4+255)/256, 256>>>((const float4*)wk, (uint2*)p_wkb, HD*CC/4, 1.f);
    k_cvtw<<<(HD*CC/4+255)/256, 256>>>((const float4*)wv, (uint2*)p_wvb, HD*CC/4, 1.f);
    k_cvtw<<<(CC*CC/4+255)/256, 256>>>((const float4*)wo, (uint2*)p_wob, CC*CC/4, 1.f);

    k_normt<<<dim3(HH/2, CC/64, BB), 256>>>(x, gn_w, gn_b);

    // Qproj: D[n][oc] = xnb . wq^T   (scale folded into wq)
    k_mma<128,128,0><<<dim3(CC/128, NN/128, BB), 256>>>(
        (const ushort_t*)p_xnb, (const ushort_t*)p_wqb, p_qb,
        (size_t)NN*CC, 0, (size_t)NN*CC, CC, nullptr, nullptr);
    // Kproj: D[m][d] = xdsb . wk^T
    k_mma<128,64,0><<<dim3(HD/64, MM/128, BB), 128>>>(
        (const ushort_t*)p_xdsb, (const ushort_t*)p_wkb, p_kb,
        (size_t)MM*CC, 0, (size_t)MM*HD, HD, nullptr, nullptr);
    // Vproj: D[d][m] = wv . xdsb^T
    k_mma<64,128,0><<<dim3(MM/128, HD/64, BB), 128>>>(
        (const ushort_t*)p_wvb, (const ushort_t*)p_xdsb, p_vb,
        0, (size_t)MM*CC, (size_t)HD*MM, MM, nullptr, nullptr);

    k_attn_mma<<<dim3(NN/128, NHD, BB), 256>>>();

    // Oproj: out[oc][n] = x + gamma[oc] * (wo . aob^T)
    k_mma<128,128,1><<<dim3(NN/128, CC/128, BB), 256>>>(
        (const ushort_t*)p_wob, (const ushort_t*)p_aob, out,
        0, (size_t)NN*CC, (size_t)CC*NN, NN, x, gamma);
}